// round 4
// baseline (speedup 1.0000x reference)
#include <cuda_runtime.h>

// 2-level 3D inverse db4 DWT, each level fully fused in one smem-tiled kernel.
// out[i] = sum_d lo[(i>>1)+d]*CLO[i&1][d] + hi[(i>>1)+d]*CHI[i&1][d]
// (conv_transpose stride 2, pad L-2; window always in-bounds for full tiles,
//  partial tiles are zero-padded which never feeds valid outputs)

#define BC 16            // batch*channels
#define TS 16            // output tile edge
#define HT 8             // output pairs per axis (TS/2)
#define EX 11            // input halo extent per axis (TS/2 + 3)

// db4 reconstruction coeffs: CLO[p][d] = g0[6+p-2d], CHI[p][d] = g1[6+p-2d]
// Literal constants -> FFMA-imm form (rt_SMSP = 1).
__device__ __constant__ float dummy_keep; // (nothing)

#define CLO00  0.032883011666982945f
#define CLO01 -0.18703481171888114f
#define CLO02  0.6308807679295904f
#define CLO03  0.23037781330885523f
#define CLO10 -0.010597401784997278f
#define CLO11  0.030841381835986965f
#define CLO12 -0.02798376941698385f
#define CLO13  0.7148465705525415f
#define CHI00  0.7148465705525415f
#define CHI01 -0.02798376941698385f
#define CHI02  0.030841381835986965f
#define CHI03 -0.010597401784997278f
#define CHI10 -0.23037781330885523f
#define CHI11 -0.6308807679295904f
#define CHI12  0.18703481171888114f
#define CHI13 -0.032883011666982945f

// Synthesize one pair of outputs from window base w (l[w..w+3], h[w..w+3])
#define SYNTH_PAIR(l, h, w, o0, o1)                                   \
    do {                                                              \
        o0 = l[w+0]*CLO00 + l[w+1]*CLO01 + l[w+2]*CLO02 + l[w+3]*CLO03 \
           + h[w+0]*CHI00 + h[w+1]*CHI01 + h[w+2]*CHI02 + h[w+3]*CHI03; \
        o1 = l[w+0]*CLO10 + l[w+1]*CLO11 + l[w+2]*CLO12 + l[w+3]*CLO13 \
           + h[w+0]*CHI10 + h[w+1]*CHI11 + h[w+2]*CHI12 + h[w+3]*CHI13; \
    } while (0)

// Level-1 intermediate: (16, 66, 66, 66)
__device__ float g_LL[(size_t)BC * 66 * 66 * 66];

// Smem partition sizes (floats)
#define S_B (8 * EX * EX * EX)          // band halos   [8][EX][EX][EX]
#define S_T (4 * EX * EX * 17)          // x-synth out  [4][EX][EX][17]
#define S_U (2 * EX * TS * 17)          // y-synth out  [2][EX][TS][17]
#define SMEM_FLOATS (S_B + S_T + S_U)
#define SMEM_BYTES  (SMEM_FLOATS * 4)

template<bool LOW_LL, bool OUT_LL>
__global__ __launch_bounds__(256, 2)
void k_fused(const float* __restrict__ low_in,
             const float* __restrict__ highs,
             float* __restrict__ out_in,
             int N, int M, int nt) {
    extern __shared__ float sm[];
    float* sB = sm;
    float* sT = sB + S_B;
    float* sU = sT + S_T;

    const float* low = LOW_LL ? g_LL : low_in;
    float* out = OUT_LL ? g_LL : out_in;

    int tid = threadIdx.x;
    int bi = blockIdx.x;
    int tx = bi % nt; bi /= nt;
    int ty = bi % nt; bi /= nt;
    int tz = bi % nt; bi /= nt;
    int b  = bi;

    const int ox0 = tx * TS, oy0 = ty * TS, oz0 = tz * TS;
    const int ibx = ox0 >> 1, iby = oy0 >> 1, ibz = oz0 >> 1;
    const size_t V = (size_t)N * N * N;

    // ---------- fill: 8 band halos (zero-padded OOB) ----------
    for (int s = tid; s < 8 * EX * EX * TS; s += 256) {
        int x = s & 15;
        if (x < EX) {
            int rid = s >> 4;
            int by = rid % EX; rid /= EX;
            int bz = rid % EX; rid /= EX;
            int band = rid;
            const float* p = (band == 0) ? (low + (size_t)b * V)
                                         : (highs + ((size_t)b * 7 + (band - 1)) * V);
            int gz = ibz + bz, gy = iby + by, gx = ibx + x;
            float v = (gz < N && gy < N && gx < N)
                        ? p[((size_t)gz * N + gy) * N + gx] : 0.f;
            sB[((band * EX + bz) * EX + by) * EX + x] = v;
        }
    }
    __syncthreads();

    // ---------- stage x: 4 pairs, each thread owns a row ----------
    for (int r = tid; r < 4 * EX * EX; r += 256) {
        int by = r % EX;
        int bz = (r / EX) % EX;
        int j  = r / (EX * EX);
        const float* lo = &sB[(((2 * j)     * EX + bz) * EX + by) * EX];
        const float* hi = &sB[(((2 * j + 1) * EX + bz) * EX + by) * EX];
        float l[EX], h[EX];
#pragma unroll
        for (int k = 0; k < EX; ++k) { l[k] = lo[k]; h[k] = hi[k]; }
        float* dst = &sT[((j * EX + bz) * EX + by) * 17];
#pragma unroll
        for (int px = 0; px < HT; ++px) {
            float o0, o1;
            SYNTH_PAIR(l, h, px, o0, o1);
            dst[2 * px]     = o0;
            dst[2 * px + 1] = o1;
        }
    }
    __syncthreads();

    // ---------- stage y: 2 pairs, each thread owns a column ----------
    for (int r = tid; r < 2 * EX * TS; r += 256) {
        int x  = r & 15;
        int bz = (r >> 4) % EX;
        int j  = r / (16 * EX);
        const float* lo = &sT[((2 * j)     * EX + bz) * EX * 17 + x];
        const float* hi = &sT[((2 * j + 1) * EX + bz) * EX * 17 + x];
        float l[EX], h[EX];
#pragma unroll
        for (int k = 0; k < EX; ++k) { l[k] = lo[k * 17]; h[k] = hi[k * 17]; }
        float* dst = &sU[(j * EX + bz) * TS * 17 + x];
#pragma unroll
        for (int py = 0; py < HT; ++py) {
            float o0, o1;
            SYNTH_PAIR(l, h, py, o0, o1);
            dst[(2 * py) * 17]     = o0;
            dst[(2 * py + 1) * 17] = o1;
        }
    }
    __syncthreads();

    // ---------- stage z + global store: 256 threads = 16x16 plane ----------
    {
        int x = tid & 15, y = tid >> 4;
        float l[EX], h[EX];
#pragma unroll
        for (int k = 0; k < EX; ++k) {
            l[k] = sU[(k * TS + y) * 17 + x];
            h[k] = sU[((EX + k) * TS + y) * 17 + x];
        }
        int gx = ox0 + x, gy = oy0 + y;
        bool okxy = (gx < M) && (gy < M);
        size_t plane = (size_t)M * M;
        size_t obase = ((size_t)b * M + oz0) * plane + (size_t)gy * M + gx;
#pragma unroll
        for (int pz = 0; pz < HT; ++pz) {
            float o0, o1;
            SYNTH_PAIR(l, h, pz, o0, o1);
            if (okxy) {
                if (oz0 + 2 * pz     < M) out[obase + (size_t)(2 * pz)     * plane] = o0;
                if (oz0 + 2 * pz + 1 < M) out[obase + (size_t)(2 * pz + 1) * plane] = o1;
            }
        }
    }
}

extern "C" void kernel_launch(void* const* d_in, const int* in_sizes, int n_in,
                              void* d_out, int out_size) {
    const float *yl = nullptr, *yh0 = nullptr, *yh1 = nullptr;
    for (int i = 0; i < n_in; ++i) {
        if      (in_sizes[i] == 746496)   yl  = (const float*)d_in[i];  // (2,8,36,36,36)
        else if (in_sizes[i] == 32199552) yh0 = (const float*)d_in[i];  // (2,8,7,66,66,66)
        else if (in_sizes[i] == 5225472)  yh1 = (const float*)d_in[i];  // (2,8,7,36,36,36)
    }
    float* out = (float*)d_out;

    static bool attr_done = false;
    if (!attr_done) {
        cudaFuncSetAttribute(k_fused<false, true>,
                             cudaFuncAttributeMaxDynamicSharedMemorySize, SMEM_BYTES);
        cudaFuncSetAttribute(k_fused<true, false>,
                             cudaFuncAttributeMaxDynamicSharedMemorySize, SMEM_BYTES);
        attr_done = true;
    }

    // Level 1: 36 -> 66  (low=yl, highs=yh1, out=g_LL)
    {
        int nt = (66 + TS - 1) / TS;  // 5
        k_fused<false, true><<<nt * nt * nt * BC, 256, SMEM_BYTES>>>(yl, yh1, nullptr, 36, 66, nt);
    }
    // Level 0: 66 -> 126 (low=g_LL, highs=yh0, out=d_out)
    {
        int nt = (126 + TS - 1) / TS; // 8
        k_fused<true, false><<<nt * nt * nt * BC, 256, SMEM_BYTES>>>(nullptr, yh0, out, 66, 126, nt);
    }
}

// round 5
// speedup vs baseline: 5.4457x; 5.4457x over previous
#include <cuda_runtime.h>

// 2-level 3D inverse db4 DWT.
// Per level: kernel A fuses x+y synthesis per z-slice (smem), kernel B streams
// z synthesis with each thread owning a full z-column (rolling 4-tap window).
// out[i] = sum_d lo[(i>>1)+d]*CLO[i&1][d] + hi[(i>>1)+d]*CHI[i&1][d]
// (conv_transpose stride 2, pad L-2; all windows provably in-bounds)

#define BC 16  // batch * channels

// db4: CLO[p][d] = g0[6+p-2d], CHI[p][d] = g1[6+p-2d]; literals -> FFMA-imm
#define CLO00  0.032883011666982945f
#define CLO01 -0.18703481171888114f
#define CLO02  0.6308807679295904f
#define CLO03  0.23037781330885523f
#define CLO10 -0.010597401784997278f
#define CLO11  0.030841381835986965f
#define CLO12 -0.02798376941698385f
#define CLO13  0.7148465705525415f
#define CHI00  0.7148465705525415f
#define CHI01 -0.02798376941698385f
#define CHI02  0.030841381835986965f
#define CHI03 -0.010597401784997278f
#define CHI10 -0.23037781330885523f
#define CHI11 -0.6308807679295904f
#define CHI12  0.18703481171888114f
#define CHI13 -0.032883011666982945f

#define SYNTH(l0,l1,l2,l3,h0,h1,h2,h3,o0,o1)                              \
    do {                                                                  \
        o0 = l0*CLO00 + l1*CLO01 + l2*CLO02 + l3*CLO03                    \
           + h0*CHI00 + h1*CHI01 + h2*CHI02 + h3*CHI03;                   \
        o1 = l0*CLO10 + l1*CLO11 + l2*CLO12 + l3*CLO13                    \
           + h0*CHI10 + h1*CHI11 + h2*CHI12 + h3*CHI13;                   \
    } while (0)

// Scratch: xy-fused output [2][BC][Nz][M][M] (sized for level 0), + level-1 LL
__device__ float g_U[2ull * BC * 66 * 126 * 126];
__device__ float g_LL[(size_t)BC * 66 * 66 * 66];

// ---------------- Kernel A: fused x+y synthesis for one z-slice ----------------
// grid = (Nz, 2 trees, BC). smem t: [2][N][M+1].
// Tree i consumes bands 4i..4i+3 (band 0 = low, band g>0 = highs[g-1]).
template<int N, bool LOW_LL>
__global__ __launch_bounds__(256)
void k_xy(const float* __restrict__ low_in, const float* __restrict__ highs) {
    constexpr int M  = 2 * N - 6;
    constexpr int MP = M + 1;      // odd -> conflict-free column reads
    constexpr int P  = N - 3;      // output pairs per axis
    extern __shared__ float t[];   // 2*N*MP floats

    const float* low = LOW_LL ? g_LL : low_in;
    const int z = blockIdx.x, i = blockIdx.y, b = blockIdx.z;
    const int tid = threadIdx.x;
    const size_t V  = (size_t)N * N * N;
    const size_t zb = (size_t)z * N * N;

    // ---- stage x: pair-threads along rows; write t[j][y][0..M) ----
    {
        const int px = tid & 63;
        const int y0 = tid >> 6;
#pragma unroll
        for (int j = 0; j < 2; ++j) {
            const int gl = 4 * i + 2 * j;
            const float* lo = (gl == 0) ? (low + (size_t)b * V)
                                        : (highs + ((size_t)b * 7 + (gl - 1)) * V);
            const float* hi = highs + ((size_t)b * 7 + gl) * V;
            if (px < P) {
                for (int y = y0; y < N; y += 4) {
                    const float* lr = lo + zb + (size_t)y * N + px;
                    const float* hr = hi + zb + (size_t)y * N + px;
                    float l0 = lr[0], l1 = lr[1], l2 = lr[2], l3 = lr[3];
                    float h0 = hr[0], h1 = hr[1], h2 = hr[2], h3 = hr[3];
                    float o0, o1;
                    SYNTH(l0, l1, l2, l3, h0, h1, h2, h3, o0, o1);
                    float* d = &t[(j * N + y) * MP + 2 * px];
                    d[0] = o0; d[1] = o1;
                }
            }
        }
    }
    __syncthreads();

    // ---- stage y: pair-threads along columns; write g_U[i][b][z][*][*] ----
    {
        const int x   = tid & 127;
        const int py0 = tid >> 7;
        if (x < M) {
            float* ub = g_U + ((((size_t)i * BC + b) * N + z) * M) * M + x;
            for (int py = py0; py < P; py += 2) {
                const float* c0 = &t[py * MP + x];            // tree-lo (j=0)
                const float* c1 = &t[(N + py) * MP + x];      // tree-hi (j=1)
                float l0 = c0[0], l1 = c0[MP], l2 = c0[2 * MP], l3 = c0[3 * MP];
                float h0 = c1[0], h1 = c1[MP], h2 = c1[2 * MP], h3 = c1[3 * MP];
                float o0, o1;
                SYNTH(l0, l1, l2, l3, h0, h1, h2, h3, o0, o1);
                float* d = ub + (size_t)(2 * py) * M;
                d[0] = o0; d[M] = o1;
            }
        }
    }
}

// ---------------- Kernel B: streaming z synthesis, thread owns a z-column ----------------
// g_U[0][b] = lo tree, g_U[1][b] = hi tree, each [NZ][plane]. Every input element
// is loaded exactly once (rolling 4-tap register window); all accesses coalesced.
template<int NZ, bool TO_LL>
__global__ __launch_bounds__(256)
void k_z(float* __restrict__ out_in, int plane) {
    const int pix = blockIdx.x * 256 + threadIdx.x;
    if (pix >= plane) return;
    const int b = blockIdx.y;
    constexpr int MZ = 2 * NZ - 6;

    float* out = TO_LL ? g_LL : out_in;
    const float* lo = g_U + (size_t)b * NZ * plane + pix;
    const float* hi = g_U + ((size_t)BC + b) * (size_t)NZ * plane + pix;
    float* ob = out + (size_t)b * MZ * plane + pix;

    float l0 = lo[0], l1 = lo[plane], l2 = lo[2 * (size_t)plane];
    float h0 = hi[0], h1 = hi[plane], h2 = hi[2 * (size_t)plane];
#pragma unroll 3
    for (int bz = 0; bz < NZ - 3; ++bz) {
        float l3 = lo[(size_t)(bz + 3) * plane];
        float h3 = hi[(size_t)(bz + 3) * plane];
        float o0, o1;
        SYNTH(l0, l1, l2, l3, h0, h1, h2, h3, o0, o1);
        ob[(size_t)(2 * bz) * plane]     = o0;
        ob[(size_t)(2 * bz + 1) * plane] = o1;
        l0 = l1; l1 = l2; l2 = l3;
        h0 = h1; h1 = h2; h2 = h3;
    }
}

extern "C" void kernel_launch(void* const* d_in, const int* in_sizes, int n_in,
                              void* d_out, int out_size) {
    const float *yl = nullptr, *yh0 = nullptr, *yh1 = nullptr;
    for (int i = 0; i < n_in; ++i) {
        if      (in_sizes[i] == 746496)   yl  = (const float*)d_in[i];  // (2,8,36,36,36)
        else if (in_sizes[i] == 32199552) yh0 = (const float*)d_in[i];  // (2,8,7,66,66,66)
        else if (in_sizes[i] == 5225472)  yh1 = (const float*)d_in[i];  // (2,8,7,36,36,36)
    }
    float* out = (float*)d_out;

    constexpr int SMEM1 = 2 * 36 * 67 * 4;   // 19,296 B
    constexpr int SMEM0 = 2 * 66 * 127 * 4;  // 67,056 B
    static bool attr_done = false;
    if (!attr_done) {
        cudaFuncSetAttribute(k_xy<66, true>,
                             cudaFuncAttributeMaxDynamicSharedMemorySize, SMEM0);
        attr_done = true;
    }

    // ---- Level 1: 36 -> 66 ----
    k_xy<36, false><<<dim3(36, 2, BC), 256, SMEM1>>>(yl, yh1);
    {
        int plane = 66 * 66;                       // 4356
        k_z<36, true><<<dim3((plane + 255) / 256, BC), 256>>>(nullptr, plane);
    }

    // ---- Level 0: 66 -> 126 ----
    k_xy<66, true><<<dim3(66, 2, BC), 256, SMEM0>>>(nullptr, yh0);
    {
        int plane = 126 * 126;                     // 15876
        k_z<66, false><<<dim3((plane + 255) / 256, BC), 256>>>(out, plane);
    }
}

// round 7
// speedup vs baseline: 6.2411x; 1.1461x over previous
#include <cuda_runtime.h>

// 2-level 3D inverse db4 DWT.
// Per level: kernel A fuses x+y synthesis per z-slice (smem), kernel B streams
// z synthesis with each thread owning two adjacent z-columns (float2).
// out[i] = sum_d lo[(i>>1)+d]*CLO[i&1][d] + hi[(i>>1)+d]*CHI[i&1][d]

#define BC 16  // batch * channels

// db4: CLO[p][d] = g0[6+p-2d], CHI[p][d] = g1[6+p-2d]; literals -> FFMA-imm
#define CLO00  0.032883011666982945f
#define CLO01 -0.18703481171888114f
#define CLO02  0.6308807679295904f
#define CLO03  0.23037781330885523f
#define CLO10 -0.010597401784997278f
#define CLO11  0.030841381835986965f
#define CLO12 -0.02798376941698385f
#define CLO13  0.7148465705525415f
#define CHI00  0.7148465705525415f
#define CHI01 -0.02798376941698385f
#define CHI02  0.030841381835986965f
#define CHI03 -0.010597401784997278f
#define CHI10 -0.23037781330885523f
#define CHI11 -0.6308807679295904f
#define CHI12  0.18703481171888114f
#define CHI13 -0.032883011666982945f

#define SYNTH(l0,l1,l2,l3,h0,h1,h2,h3,o0,o1)                              \
    do {                                                                  \
        o0 = l0*CLO00 + l1*CLO01 + l2*CLO02 + l3*CLO03                    \
           + h0*CHI00 + h1*CHI01 + h2*CHI02 + h3*CHI03;                   \
        o1 = l0*CLO10 + l1*CLO11 + l2*CLO12 + l3*CLO13                    \
           + h0*CHI10 + h1*CHI11 + h2*CHI12 + h3*CHI13;                   \
    } while (0)

// Scratch: xy-fused output [2][BC][Nz][M][M] (sized for level 0), + level-1 LL
__device__ float g_U[2ull * BC * 66 * 126 * 126];
__device__ float g_LL[(size_t)BC * 66 * 66 * 66];

// ---------------- Kernel A: fused x+y synthesis for one z-slice ----------------
// grid = (Nz, 2 trees, BC), 512 threads. smem t: [2][N][M+1].
// Tree i consumes bands 4i..4i+3 (band 0 = low, band g>0 = highs[g-1]).
template<int N, bool LOW_LL>
__global__ __launch_bounds__(512)
void k_xy(const float* __restrict__ low_in, const float* __restrict__ highs) {
    constexpr int M  = 2 * N - 6;
    constexpr int MP = M + 1;      // odd -> conflict-free column reads
    constexpr int P  = N - 3;      // output pairs per axis
    extern __shared__ float t[];   // 2*N*MP floats

    const float* low = LOW_LL ? g_LL : low_in;
    const int z = blockIdx.x, i = blockIdx.y, b = blockIdx.z;
    const int tid = threadIdx.x;
    const size_t V  = (size_t)N * N * N;
    const size_t zb = (size_t)z * N * N;

    // ---- stage x: pair-threads along rows; write t[j][y][0..M) ----
    {
        const int px = tid & 63;
        const int y0 = tid >> 6;        // 0..7
#pragma unroll
        for (int j = 0; j < 2; ++j) {
            const int gl = 4 * i + 2 * j;
            const float* lo = (gl == 0) ? (low + (size_t)b * V)
                                        : (highs + ((size_t)b * 7 + (gl - 1)) * V);
            const float* hi = highs + ((size_t)b * 7 + gl) * V;
            if (px < P) {
                for (int y = y0; y < N; y += 8) {
                    const float* lr = lo + zb + (size_t)y * N + px;
                    const float* hr = hi + zb + (size_t)y * N + px;
                    float l0 = lr[0], l1 = lr[1], l2 = lr[2], l3 = lr[3];
                    float h0 = hr[0], h1 = hr[1], h2 = hr[2], h3 = hr[3];
                    float o0, o1;
                    SYNTH(l0, l1, l2, l3, h0, h1, h2, h3, o0, o1);
                    float* d = &t[(j * N + y) * MP + 2 * px];
                    d[0] = o0; d[1] = o1;
                }
            }
        }
    }
    __syncthreads();

    // ---- stage y: pair-threads along columns; write g_U[i][b][z][*][*] ----
    {
        const int x   = tid & 127;
        const int py0 = tid >> 7;       // 0..3
        if (x < M) {
            float* ub = g_U + ((((size_t)i * BC + b) * N + z) * M) * M + x;
            for (int py = py0; py < P; py += 4) {
                const float* c0 = &t[py * MP + x];            // tree-lo (j=0)
                const float* c1 = &t[(N + py) * MP + x];      // tree-hi (j=1)
                float l0 = c0[0], l1 = c0[MP], l2 = c0[2 * MP], l3 = c0[3 * MP];
                float h0 = c1[0], h1 = c1[MP], h2 = c1[2 * MP], h3 = c1[3 * MP];
                float o0, o1;
                SYNTH(l0, l1, l2, l3, h0, h1, h2, h3, o0, o1);
                float* d = ub + (size_t)(2 * py) * M;
                d[0] = o0; d[M] = o1;
            }
        }
    }
}

// ---------------- Kernel B: streaming z synthesis, float2 per thread ----------------
// g_U[0][b] = lo tree, g_U[1][b] = hi tree, each [NZ][plane]. Every input element
// loaded exactly once (rolling 4-tap window); LDG.64/STG.64, fully coalesced.
template<int NZ, bool TO_LL>
__global__ __launch_bounds__(256)
void k_z(float* __restrict__ out_in, int plane2) {   // plane2 = plane/2
    const int pix = blockIdx.x * 256 + threadIdx.x;
    if (pix >= plane2) return;
    const int b = blockIdx.y;
    constexpr int MZ = 2 * NZ - 6;

    float* out = TO_LL ? g_LL : out_in;
    const float2* lo = (const float2*)g_U + (size_t)b * NZ * plane2 + pix;
    const float2* hi = (const float2*)g_U + ((size_t)BC + b) * (size_t)NZ * plane2 + pix;
    float2* ob = (float2*)out + (size_t)b * MZ * plane2 + pix;

    float2 l0 = lo[0], l1 = lo[plane2], l2 = lo[2 * (size_t)plane2];
    float2 h0 = hi[0], h1 = hi[plane2], h2 = hi[2 * (size_t)plane2];
#pragma unroll 3
    for (int bz = 0; bz < NZ - 3; ++bz) {
        float2 l3 = lo[(size_t)(bz + 3) * plane2];
        float2 h3 = hi[(size_t)(bz + 3) * plane2];
        float2 o0, o1;
        SYNTH(l0.x, l1.x, l2.x, l3.x, h0.x, h1.x, h2.x, h3.x, o0.x, o1.x);
        SYNTH(l0.y, l1.y, l2.y, l3.y, h0.y, h1.y, h2.y, h3.y, o0.y, o1.y);
        ob[(size_t)(2 * bz) * plane2]     = o0;
        ob[(size_t)(2 * bz + 1) * plane2] = o1;
        l0 = l1; l1 = l2; l2 = l3;
        h0 = h1; h1 = h2; h2 = h3;
    }
}

extern "C" void kernel_launch(void* const* d_in, const int* in_sizes, int n_in,
                              void* d_out, int out_size) {
    const float *yl = nullptr, *yh0 = nullptr, *yh1 = nullptr;
    for (int i = 0; i < n_in; ++i) {
        if      (in_sizes[i] == 746496)   yl  = (const float*)d_in[i];  // (2,8,36,36,36)
        else if (in_sizes[i] == 32199552) yh0 = (const float*)d_in[i];  // (2,8,7,66,66,66)
        else if (in_sizes[i] == 5225472)  yh1 = (const float*)d_in[i];  // (2,8,7,36,36,36)
    }
    float* out = (float*)d_out;

    constexpr int SMEM1 = 2 * 36 * 67 * 4;   // 19,296 B
    constexpr int SMEM0 = 2 * 66 * 127 * 4;  // 67,056 B
    static bool attr_done = false;
    if (!attr_done) {
        cudaFuncSetAttribute(k_xy<66, true>,
                             cudaFuncAttributeMaxDynamicSharedMemorySize, SMEM0);
        attr_done = true;
    }

    // ---- Level 1: 36 -> 66 ----
    k_xy<36, false><<<dim3(36, 2, BC), 512, SMEM1>>>(yl, yh1);
    {
        int plane2 = 66 * 66 / 2;                  // 2178
        k_z<36, true><<<dim3((plane2 + 255) / 256, BC), 256>>>(nullptr, plane2);
    }

    // ---- Level 0: 66 -> 126 ----
    k_xy<66, true><<<dim3(66, 2, BC), 512, SMEM0>>>(nullptr, yh0);
    {
        int plane2 = 126 * 126 / 2;                // 7938
        k_z<66, false><<<dim3((plane2 + 255) / 256, BC), 256>>>(out, plane2);
    }
}

// round 8
// speedup vs baseline: 6.5708x; 1.0528x over previous
#include <cuda_runtime.h>

// 2-level 3D inverse db4 DWT.
// Per level: kernel A fuses x+y synthesis per z-slice (smem), kernel B streams
// z synthesis, float2 per thread, z-range split into segments for occupancy.
// out[i] = sum_d lo[(i>>1)+d]*CLO[i&1][d] + hi[(i>>1)+d]*CHI[i&1][d]

#define BC 16  // batch * channels

// db4: CLO[p][d] = g0[6+p-2d], CHI[p][d] = g1[6+p-2d]; literals -> FFMA-imm
#define CLO00  0.032883011666982945f
#define CLO01 -0.18703481171888114f
#define CLO02  0.6308807679295904f
#define CLO03  0.23037781330885523f
#define CLO10 -0.010597401784997278f
#define CLO11  0.030841381835986965f
#define CLO12 -0.02798376941698385f
#define CLO13  0.7148465705525415f
#define CHI00  0.7148465705525415f
#define CHI01 -0.02798376941698385f
#define CHI02  0.030841381835986965f
#define CHI03 -0.010597401784997278f
#define CHI10 -0.23037781330885523f
#define CHI11 -0.6308807679295904f
#define CHI12  0.18703481171888114f
#define CHI13 -0.032883011666982945f

#define SYNTH(l0,l1,l2,l3,h0,h1,h2,h3,o0,o1)                              \
    do {                                                                  \
        o0 = l0*CLO00 + l1*CLO01 + l2*CLO02 + l3*CLO03                    \
           + h0*CHI00 + h1*CHI01 + h2*CHI02 + h3*CHI03;                   \
        o1 = l0*CLO10 + l1*CLO11 + l2*CLO12 + l3*CLO13                    \
           + h0*CHI10 + h1*CHI11 + h2*CHI12 + h3*CHI13;                   \
    } while (0)

// Scratch: xy-fused output [2][BC][Nz][M][M] (sized for level 0), + level-1 LL
__device__ float g_U[2ull * BC * 66 * 126 * 126];
__device__ float g_LL[(size_t)BC * 66 * 66 * 66];

// ---------------- Kernel A: fused x+y synthesis for one z-slice ----------------
// grid = (Nz, 2 trees, BC), 512 threads. smem t: [2][N][M+1].
// Tree i consumes bands 4i..4i+3 (band 0 = low, band g>0 = highs[g-1]).
// Stage x processes BOTH sub-trees in one loop so 16 independent LDGs issue
// back-to-back (front-batched MLP).
template<int N, bool LOW_LL>
__global__ __launch_bounds__(512)
void k_xy(const float* __restrict__ low_in, const float* __restrict__ highs) {
    constexpr int M  = 2 * N - 6;
    constexpr int MP = M + 1;      // odd -> conflict-free column reads
    constexpr int P  = N - 3;      // output pairs per axis
    extern __shared__ float t[];   // 2*N*MP floats

    const float* low = LOW_LL ? g_LL : low_in;
    const int z = blockIdx.x, i = blockIdx.y, b = blockIdx.z;
    const int tid = threadIdx.x;
    const size_t V  = (size_t)N * N * N;
    const size_t zb = (size_t)z * N * N;

    // ---- stage x: pair-threads along rows; write t[j][y][0..M) ----
    {
        const int px = tid & 63;
        const int y0 = tid >> 6;        // 0..7
        const int gl0 = 4 * i;          // sub-tree 0 bands (gl0, gl0+1)
        const float* lo0 = (gl0 == 0) ? (low + (size_t)b * V)
                                      : (highs + ((size_t)b * 7 + (gl0 - 1)) * V);
        const float* hi0 = highs + ((size_t)b * 7 + gl0) * V;
        const float* lo1 = highs + ((size_t)b * 7 + (4 * i + 1)) * V;
        const float* hi1 = highs + ((size_t)b * 7 + (4 * i + 2)) * V;
        if (px < P) {
            for (int y = y0; y < N; y += 8) {
                const size_t ro = zb + (size_t)y * N + px;
                const float* a = lo0 + ro;  const float* c = hi0 + ro;
                const float* e = lo1 + ro;  const float* f = hi1 + ro;
                float a0 = a[0], a1 = a[1], a2 = a[2], a3 = a[3];
                float c0 = c[0], c1 = c[1], c2 = c[2], c3 = c[3];
                float e0 = e[0], e1 = e[1], e2 = e[2], e3 = e[3];
                float f0 = f[0], f1 = f[1], f2 = f[2], f3 = f[3];
                float o0, o1, p0, p1;
                SYNTH(a0, a1, a2, a3, c0, c1, c2, c3, o0, o1);
                SYNTH(e0, e1, e2, e3, f0, f1, f2, f3, p0, p1);
                float* d0 = &t[y * MP + 2 * px];
                float* d1 = &t[(N + y) * MP + 2 * px];
                d0[0] = o0; d0[1] = o1;
                d1[0] = p0; d1[1] = p1;
            }
        }
    }
    __syncthreads();

    // ---- stage y: pair-threads along columns; write g_U[i][b][z][*][*] ----
    {
        const int x   = tid & 127;
        const int py0 = tid >> 7;       // 0..3
        if (x < M) {
            float* ub = g_U + ((((size_t)i * BC + b) * N + z) * M) * M + x;
            for (int py = py0; py < P; py += 4) {
                const float* c0 = &t[py * MP + x];            // sub-tree lo
                const float* c1 = &t[(N + py) * MP + x];      // sub-tree hi
                float l0 = c0[0], l1 = c0[MP], l2 = c0[2 * MP], l3 = c0[3 * MP];
                float h0 = c1[0], h1 = c1[MP], h2 = c1[2 * MP], h3 = c1[3 * MP];
                float o0, o1;
                SYNTH(l0, l1, l2, l3, h0, h1, h2, h3, o0, o1);
                float* d = ub + (size_t)(2 * py) * M;
                d[0] = o0; d[M] = o1;
            }
        }
    }
}

// ---------------- Kernel B: streaming z synthesis, float2, z-segmented ----------------
// g_U[0][b] = lo tree, g_U[1][b] = hi tree, each [NZ][plane]. grid.y = segment,
// grid.z = b. Each segment handles output pairs [p0, p1) (3-slice read overlap).
template<int NZ, int SEG, bool TO_LL>
__global__ __launch_bounds__(256)
void k_z(float* __restrict__ out_in, int plane2) {   // plane2 = plane/2
    const int pix = blockIdx.x * 256 + threadIdx.x;
    if (pix >= plane2) return;
    const int seg = blockIdx.y;
    const int b   = blockIdx.z;
    constexpr int MZ = 2 * NZ - 6;
    constexpr int P  = NZ - 3;
    constexpr int CH = (P + SEG - 1) / SEG;

    const int p0 = seg * CH;
    const int p1 = (p0 + CH < P) ? (p0 + CH) : P;

    float* out = TO_LL ? g_LL : out_in;
    const float2* lo = (const float2*)g_U + (size_t)b * NZ * plane2 + pix;
    const float2* hi = (const float2*)g_U + ((size_t)BC + b) * (size_t)NZ * plane2 + pix;
    float2* ob = (float2*)out + (size_t)b * MZ * plane2 + pix;

    float2 l0 = lo[(size_t)p0 * plane2];
    float2 l1 = lo[(size_t)(p0 + 1) * plane2];
    float2 l2 = lo[(size_t)(p0 + 2) * plane2];
    float2 h0 = hi[(size_t)p0 * plane2];
    float2 h1 = hi[(size_t)(p0 + 1) * plane2];
    float2 h2 = hi[(size_t)(p0 + 2) * plane2];
#pragma unroll 4
    for (int bz = p0; bz < p1; ++bz) {
        float2 l3 = lo[(size_t)(bz + 3) * plane2];
        float2 h3 = hi[(size_t)(bz + 3) * plane2];
        float2 o0, o1;
        SYNTH(l0.x, l1.x, l2.x, l3.x, h0.x, h1.x, h2.x, h3.x, o0.x, o1.x);
        SYNTH(l0.y, l1.y, l2.y, l3.y, h0.y, h1.y, h2.y, h3.y, o0.y, o1.y);
        ob[(size_t)(2 * bz) * plane2]     = o0;
        ob[(size_t)(2 * bz + 1) * plane2] = o1;
        l0 = l1; l1 = l2; l2 = l3;
        h0 = h1; h1 = h2; h2 = h3;
    }
}

extern "C" void kernel_launch(void* const* d_in, const int* in_sizes, int n_in,
                              void* d_out, int out_size) {
    const float *yl = nullptr, *yh0 = nullptr, *yh1 = nullptr;
    for (int i = 0; i < n_in; ++i) {
        if      (in_sizes[i] == 746496)   yl  = (const float*)d_in[i];  // (2,8,36,36,36)
        else if (in_sizes[i] == 32199552) yh0 = (const float*)d_in[i];  // (2,8,7,66,66,66)
        else if (in_sizes[i] == 5225472)  yh1 = (const float*)d_in[i];  // (2,8,7,36,36,36)
    }
    float* out = (float*)d_out;

    constexpr int SMEM1 = 2 * 36 * 67 * 4;   // 19,296 B
    constexpr int SMEM0 = 2 * 66 * 127 * 4;  // 67,056 B
    static bool attr_done = false;
    if (!attr_done) {
        cudaFuncSetAttribute(k_xy<66, true>,
                             cudaFuncAttributeMaxDynamicSharedMemorySize, SMEM0);
        attr_done = true;
    }

    // ---- Level 1: 36 -> 66 ----
    k_xy<36, false><<<dim3(36, 2, BC), 512, SMEM1>>>(yl, yh1);
    {
        int plane2 = 66 * 66 / 2;                  // 2178
        k_z<36, 2, true><<<dim3((plane2 + 255) / 256, 2, BC), 256>>>(nullptr, plane2);
    }

    // ---- Level 0: 66 -> 126 ----
    k_xy<66, true><<<dim3(66, 2, BC), 512, SMEM0>>>(nullptr, yh0);
    {
        int plane2 = 126 * 126 / 2;                // 7938
        k_z<66, 4, false><<<dim3((plane2 + 255) / 256, 4, BC), 256>>>(out, plane2);
    }
}